// round 6
// baseline (speedup 1.0000x reference)
#include <cuda_runtime.h>
#include <cstdint>

#define BB   256
#define NNE  65536
#define H1BINS 4096   // 12-bit level-1 (sign + 8 exp + 3 mantissa bits)

// ---------------- scratch (static device globals; no allocation) ----------------
__device__ unsigned g_keys[(size_t)BB * NNE];    // 64 MB: orderable keys
__device__ uint2    g_cand2[(size_t)BB * NNE];   // 128 MB: (key, idx) candidates (worst case)
__device__ unsigned g_hist1[BB * H1BINS];        // 4 MB : level-1 histograms
__device__ unsigned g_p1[BB];
__device__ int      g_rem[BB];
__device__ int      g_ccnt[BB];

// ---------------- helpers ----------------
__device__ __forceinline__ unsigned float_key(float w) {
    unsigned x = __float_as_uint(w);
    return x ^ ((unsigned)((int)x >> 31) | 0x80000000u);   // order-preserving
}

__device__ __forceinline__ unsigned weight_key(float u, float d) {
    // G = -log(-log(U+eps)+eps); w = G + log(D); eps = 1e-7 (match jnp expr order)
    float l1 = logf(u + 1e-7f);
    float inner = -l1 + 1e-7f;
    float G = -logf(inner);
    float w = G + logf(d);
    return float_key(w);
}

// Block-wide "find bin containing the rem-th largest" over a shared histogram.
template <int BINS, int THREADS>
__device__ __forceinline__ void select_bin(const unsigned* h, unsigned* ss, int rem,
                                           int* out_bin, int* out_rem, unsigned* out_cnt) {
    constexpr int PER = BINS / THREADS;
    int tid = threadIdx.x;
    unsigned s = 0;
#pragma unroll
    for (int j = 0; j < PER; j++) s += h[tid * PER + j];
    ss[tid] = s;
    __syncthreads();
    for (int off = 1; off < THREADS; off <<= 1) {
        unsigned add = (tid + off < THREADS) ? ss[tid + off] : 0u;
        __syncthreads();
        ss[tid] += add;
        __syncthreads();
    }
    unsigned cumGE = ss[tid];
    unsigned cumGT = (tid < THREADS - 1) ? ss[tid + 1] : 0u;
    if (cumGE >= (unsigned)rem && cumGT < (unsigned)rem) {
        unsigned cum = cumGT;
#pragma unroll
        for (int b = PER - 1; b >= 0; --b) {
            unsigned c = h[tid * PER + b];
            if (cum + c >= (unsigned)rem) {
                *out_bin = tid * PER + b;
                *out_rem = rem - (int)cum;   // 1-based rank within selected bin
                *out_cnt = c;                // elements in selected bin
                break;
            }
            cum += c;
        }
    }
}

// ---------------- K0: per-row scalars + counters ----------------
__global__ void k_init(const float* __restrict__ t, float* __restrict__ out) {
    int gid = blockIdx.x * blockDim.x + threadIdx.x;
    if (gid < BB) {
        float tv = t[gid];
        float a = 3.14159265358979323846f * tv * 0.5f;
        float r = 1.0f - cosf(a);
        int k = (int)(65536.0f * r);            // trunc like astype(int32)
        float ta = tv * 0.998f + 0.001f;
        float w = 1.5707963267948966f * sinf(3.14159265358979323846f * ta * 0.5f);
        out[(size_t)BB * NNE + gid] = w;
        g_rem[gid]  = k;
        g_p1[gid]   = 0x10000u;                 // "select nothing" default (k<=0 rows)
        g_ccnt[gid] = 0;
    }
}

// ---------------- K1: compute keys + 12-bit level-1 histogram (fused) ----------------
// 8192 elements / block (8 uint4 per thread), plain shared atomics (spread bins).
__global__ void __launch_bounds__(256) k_keys(const float* __restrict__ U,
                                              const float* __restrict__ D) {
    __shared__ unsigned h[H1BINS];
    int tid = threadIdx.x;
    for (int i = tid; i < H1BINS; i += 256) h[i] = 0u;
    __syncthreads();

    int row = blockIdx.y;
    int vbase = (row * NNE + blockIdx.x * 8192) >> 2;  // float4 index
    const float4* U4 = (const float4*)U;
    const float4* D4 = (const float4*)D;
    uint4* K4 = (uint4*)g_keys;
#pragma unroll
    for (int i = 0; i < 8; i++) {
        int vi = vbase + i * 256 + tid;
        float4 u = U4[vi];
        float4 d = D4[vi];
        uint4 kk;
        kk.x = weight_key(u.x, d.x);
        kk.y = weight_key(u.y, d.y);
        kk.z = weight_key(u.z, d.z);
        kk.w = weight_key(u.w, d.w);
        K4[vi] = kk;
        atomicAdd(&h[kk.x >> 20], 1u);
        atomicAdd(&h[kk.y >> 20], 1u);
        atomicAdd(&h[kk.z >> 20], 1u);
        atomicAdd(&h[kk.w >> 20], 1u);
    }
    __syncthreads();
    unsigned* gh = g_hist1 + row * H1BINS;
    for (int i = tid; i < H1BINS; i += 256) {
        unsigned c = h[i];
        if (c) atomicAdd(&gh[i], c);
    }
}

// ---------------- K2: level-1 bin selection (one block / row) ----------------
__global__ void __launch_bounds__(256) k_sel1() {
    int row = blockIdx.x;
    if (g_rem[row] <= 0) return;                 // p1 stays 0x10000 -> all-zero mask
    int tid = threadIdx.x;
    __shared__ unsigned sh[H1BINS];
    __shared__ unsigned ss[256];
    __shared__ int r_bin, r_rem;
    __shared__ unsigned r_cnt;
    for (int i = tid; i < H1BINS; i += 256) sh[i] = g_hist1[row * H1BINS + i];
    int rem = g_rem[row];
    __syncthreads();
    select_bin<H1BINS, 256>(sh, ss, rem, &r_bin, &r_rem, &r_cnt);
    __syncthreads();
    if (tid == 0) {
        g_p1[row]  = (unsigned)r_bin;
        g_rem[row] = r_rem;
    }
}

// ---------------- K3: fused mask write + candidate compaction ----------------
// Pure streaming: no warp collectives, no shared staging. Candidate order in
// g_cand2 is irrelevant (tie-break ranks by the stored original index), so each
// thread pushes its (rare) candidates straight to global via one atomicAdd.
__global__ void __launch_bounds__(256) k_scan(float* __restrict__ out) {
    int tid = threadIdx.x;
    int row = blockIdx.y;
    unsigned p1 = g_p1[row];
    unsigned long long lo = (unsigned long long)p1 << 20;        // bin == p1 range
    unsigned long long hi = lo + (1ull << 20);                   // (sentinel-safe in 64-bit)

    int ebase = blockIdx.x * 4096;                               // element base within row
    int vbase = (row * NNE + ebase) >> 2;
    const uint4* K4 = (const uint4*)g_keys;
    float4* O4 = (float4*)out;
    uint2* crow = g_cand2 + (size_t)row * NNE;
#pragma unroll
    for (int i = 0; i < 4; i++) {
        int vi = vbase + i * 256 + tid;
        uint4 kk = K4[vi];
        int eidx = ebase + ((i * 256 + tid) << 2);               // element index of kk.x
        unsigned vals[4] = {kk.x, kk.y, kk.z, kk.w};
        float m[4];
        unsigned ck[4], ci[4];
        int nc = 0;
#pragma unroll
        for (int j = 0; j < 4; j++) {
            unsigned long long kv = vals[j];
            m[j] = (kv >= hi) ? 1.0f : 0.0f;
            if (kv >= lo && kv < hi) { ck[nc] = vals[j]; ci[nc] = (unsigned)(eidx + j); nc++; }
        }
        O4[vi] = make_float4(m[0], m[1], m[2], m[3]);
        if (nc) {
            int base = atomicAdd(&g_ccnt[row], nc);
            for (int j = 0; j < nc; j++) crow[base + j] = make_uint2(ck[j], ci[j]);
        }
    }
}

// ---------------- K4: finalize — levels 2/3 on candidates, scatter 1s ----------------
#define TIE_CAP 4096
__global__ void __launch_bounds__(1024) k_fin(float* __restrict__ out) {
    int row = blockIdx.x;
    int C = g_ccnt[row];
    if (C == 0) return;
    int tid = threadIdx.x;
    __shared__ unsigned h[1024];
    __shared__ unsigned ss[1024];
    __shared__ int r_bin, r_rem;
    __shared__ unsigned r_cnt;
    __shared__ unsigned tie_idx[TIE_CAP];
    __shared__ int tie_cnt;
    const uint2* cand = g_cand2 + (size_t)row * NNE;
    int rem = g_rem[row];

    // level 2: key bits [19:10]
    h[tid] = 0u;
    if (tid == 0) tie_cnt = 0;
    __syncthreads();
    for (int i = tid; i < C; i += 1024)
        atomicAdd(&h[(cand[i].x >> 10) & 1023u], 1u);
    __syncthreads();
    select_bin<1024, 1024>(h, ss, rem, &r_bin, &r_rem, &r_cnt);
    __syncthreads();
    unsigned p2 = (unsigned)r_bin;
    rem = r_rem;
    __syncthreads();

    // level 3: key bits [9:0] among bin p2
    h[tid] = 0u;
    __syncthreads();
    for (int i = tid; i < C; i += 1024) {
        unsigned kv = cand[i].x;
        if (((kv >> 10) & 1023u) == p2) atomicAdd(&h[kv & 1023u], 1u);
    }
    __syncthreads();
    select_bin<1024, 1024>(h, ss, rem, &r_bin, &r_rem, &r_cnt);
    __syncthreads();

    unsigned T = (g_p1[row] << 20) | (p2 << 10) | (unsigned)r_bin;
    int need = r_rem;            // # of key==T elements to take
    int cntT = (int)r_cnt;
    float* orow = out + (size_t)row * NNE;

    if (need == cntT) {
        // no tie at boundary: all >= T selected
        for (int i = tid; i < C; i += 1024) {
            uint2 cd = cand[i];
            if (cd.x >= T) orow[cd.y] = 1.0f;
        }
    } else {
        // select all > T; gather ==T indices into shared, rank by original index
        for (int i = tid; i < C; i += 1024) {
            uint2 cd = cand[i];
            if (cd.x > T) orow[cd.y] = 1.0f;
            else if (cd.x == T) {
                int p = atomicAdd(&tie_cnt, 1);
                if (p < TIE_CAP) tie_idx[p] = cd.y;
            }
        }
        __syncthreads();
        int tc = tie_cnt < TIE_CAP ? tie_cnt : TIE_CAP;
        // stable tie-break: lowest original index first (argsort stability)
        for (int i = tid; i < tc; i += 1024) {
            unsigned my = tie_idx[i];
            int rank = 0;
            for (int j = 0; j < tc; j++) rank += (tie_idx[j] < my);
            if (rank < need) orow[my] = 1.0f;
        }
    }
}

// ---------------- launch ----------------
extern "C" void kernel_launch(void* const* d_in, const int* in_sizes, int n_in,
                              void* d_out, int out_size) {
    // metadata order: batch (unused), t, U, D
    const float* t = (const float*)d_in[1];
    const float* U = (const float*)d_in[2];
    const float* D = (const float*)d_in[3];
    float* out = (float*)d_out;

    void* hist_ptr = nullptr;
    cudaGetSymbolAddress(&hist_ptr, g_hist1);
    cudaMemsetAsync(hist_ptr, 0, (size_t)BB * H1BINS * sizeof(unsigned));

    k_init<<<1, 256>>>(t, out);
    dim3 gkeys(8, BB);
    k_keys<<<gkeys, 256>>>(U, D);
    k_sel1<<<BB, 256>>>();
    dim3 gscan(16, BB);
    k_scan<<<gscan, 256>>>(out);
    k_fin<<<BB, 1024>>>(out);
}

// round 8
// speedup vs baseline: 4.9962x; 4.9962x over previous
#include <cuda_runtime.h>
#include <cstdint>

#define BB   256
#define NNE  65536
#define H1BINS 4096   // 12-bit level-1 (sign + 8 exp + 3 mantissa bits)

// ---------------- scratch (static device globals; no allocation) ----------------
__device__ unsigned g_keys[(size_t)BB * NNE];    // 64 MB: orderable keys
__device__ uint2    g_cand2[(size_t)BB * NNE];   // 128 MB: (key, idx) candidates (worst case)
__device__ unsigned g_hist1[BB * H1BINS];        // 4 MB : level-1 histograms
__device__ unsigned g_p1[BB];
__device__ int      g_rem[BB];
__device__ int      g_ccnt[BB];

// ---------------- helpers ----------------
__device__ __forceinline__ unsigned float_key(float w) {
    unsigned x = __float_as_uint(w);
    return x ^ ((unsigned)((int)x >> 31) | 0x80000000u);   // order-preserving
}

__device__ __forceinline__ unsigned weight_key(float u, float d) {
    // G = -log(-log(U+eps)+eps); w = G + log(D); eps = 1e-7 (match jnp expr order)
    float l1 = logf(u + 1e-7f);
    float inner = -l1 + 1e-7f;
    float G = -logf(inner);
    float w = G + logf(d);
    return float_key(w);
}

// Block-wide "find bin containing the rem-th largest" over a shared histogram.
template <int BINS, int THREADS>
__device__ __forceinline__ void select_bin(const unsigned* h, unsigned* ss, int rem,
                                           int* out_bin, int* out_rem, unsigned* out_cnt) {
    constexpr int PER = BINS / THREADS;
    int tid = threadIdx.x;
    unsigned s = 0;
#pragma unroll
    for (int j = 0; j < PER; j++) s += h[tid * PER + j];
    ss[tid] = s;
    __syncthreads();
    for (int off = 1; off < THREADS; off <<= 1) {
        unsigned add = (tid + off < THREADS) ? ss[tid + off] : 0u;
        __syncthreads();
        ss[tid] += add;
        __syncthreads();
    }
    unsigned cumGE = ss[tid];
    unsigned cumGT = (tid < THREADS - 1) ? ss[tid + 1] : 0u;
    if (cumGE >= (unsigned)rem && cumGT < (unsigned)rem) {
        unsigned cum = cumGT;
#pragma unroll
        for (int b = PER - 1; b >= 0; --b) {
            unsigned c = h[tid * PER + b];
            if (cum + c >= (unsigned)rem) {
                *out_bin = tid * PER + b;
                *out_rem = rem - (int)cum;   // 1-based rank within selected bin
                *out_cnt = c;                // elements in selected bin
                break;
            }
            cum += c;
        }
    }
}

// ---------------- K0: per-row scalars + counters ----------------
__global__ void k_init(const float* __restrict__ t, float* __restrict__ out) {
    int gid = blockIdx.x * blockDim.x + threadIdx.x;
    if (gid < BB) {
        float tv = t[gid];
        float a = 3.14159265358979323846f * tv * 0.5f;
        float r = 1.0f - cosf(a);
        int k = (int)(65536.0f * r);            // trunc like astype(int32)
        float ta = tv * 0.998f + 0.001f;
        float w = 1.5707963267948966f * sinf(3.14159265358979323846f * ta * 0.5f);
        out[(size_t)BB * NNE + gid] = w;
        g_rem[gid]  = k;
        g_p1[gid]   = 0x10000u;                 // "select nothing" default (k<=0 rows)
        g_ccnt[gid] = 0;
    }
}

// ---------------- K1: compute keys + 12-bit level-1 histogram (fused) ----------------
// 8192 elements / block (8 uint4 per thread), plain shared atomics (spread bins).
__global__ void __launch_bounds__(256) k_keys(const float* __restrict__ U,
                                              const float* __restrict__ D) {
    __shared__ unsigned h[H1BINS];
    int tid = threadIdx.x;
    for (int i = tid; i < H1BINS; i += 256) h[i] = 0u;
    __syncthreads();

    int row = blockIdx.y;
    int vbase = (row * NNE + blockIdx.x * 8192) >> 2;  // float4 index
    const float4* U4 = (const float4*)U;
    const float4* D4 = (const float4*)D;
    uint4* K4 = (uint4*)g_keys;
#pragma unroll
    for (int i = 0; i < 8; i++) {
        int vi = vbase + i * 256 + tid;
        float4 u = U4[vi];
        float4 d = D4[vi];
        uint4 kk;
        kk.x = weight_key(u.x, d.x);
        kk.y = weight_key(u.y, d.y);
        kk.z = weight_key(u.z, d.z);
        kk.w = weight_key(u.w, d.w);
        K4[vi] = kk;
        atomicAdd(&h[kk.x >> 20], 1u);
        atomicAdd(&h[kk.y >> 20], 1u);
        atomicAdd(&h[kk.z >> 20], 1u);
        atomicAdd(&h[kk.w >> 20], 1u);
    }
    __syncthreads();
    unsigned* gh = g_hist1 + row * H1BINS;
    for (int i = tid; i < H1BINS; i += 256) {
        unsigned c = h[i];
        if (c) atomicAdd(&gh[i], c);
    }
}

// ---------------- K2: level-1 bin selection (one block / row) ----------------
__global__ void __launch_bounds__(256) k_sel1() {
    int row = blockIdx.x;
    if (g_rem[row] <= 0) return;                 // p1 stays 0x10000 -> all-zero mask
    int tid = threadIdx.x;
    __shared__ unsigned sh[H1BINS];
    __shared__ unsigned ss[256];
    __shared__ int r_bin, r_rem;
    __shared__ unsigned r_cnt;
    for (int i = tid; i < H1BINS; i += 256) sh[i] = g_hist1[row * H1BINS + i];
    int rem = g_rem[row];
    __syncthreads();
    select_bin<H1BINS, 256>(sh, ss, rem, &r_bin, &r_rem, &r_cnt);
    __syncthreads();
    if (tid == 0) {
        g_p1[row]  = (unsigned)r_bin;
        g_rem[row] = r_rem;
    }
}

// ---------------- K3: fused mask write + candidate compaction ----------------
// Streaming pass. Rare candidates (~2%) go straight to a shared staging buffer
// via a shared atomic counter (no ballots, no dynamic register arrays, no
// per-element global atomics). One global atomicAdd per block to flush.
// Worst case: whole 4096-element chunk in bin p1 -> staging holds 4096 (32KB).
__global__ void __launch_bounds__(256) k_scan(float* __restrict__ out) {
    __shared__ uint2 st[4096];
    __shared__ int scnt, sbase;
    int tid = threadIdx.x;
    if (tid == 0) scnt = 0;
    int row = blockIdx.y;
    unsigned p1 = g_p1[row];                     // 0x10000 sentinel -> nothing matches
    __syncthreads();

    int ebase = blockIdx.x * 4096;               // element base within row
    int vbase = (row * NNE + ebase) >> 2;
    const uint4* K4 = (const uint4*)g_keys;
    float4* O4 = (float4*)out;
#pragma unroll
    for (int i = 0; i < 4; i++) {
        int vi = vbase + i * 256 + tid;
        uint4 kk = K4[vi];
        int eidx = ebase + ((i * 256 + tid) << 2);   // element index of kk.x
        float4 m;
        m.x = ((kk.x >> 20) > p1) ? 1.0f : 0.0f;
        m.y = ((kk.y >> 20) > p1) ? 1.0f : 0.0f;
        m.z = ((kk.z >> 20) > p1) ? 1.0f : 0.0f;
        m.w = ((kk.w >> 20) > p1) ? 1.0f : 0.0f;
        if ((kk.x >> 20) == p1) st[atomicAdd(&scnt, 1)] = make_uint2(kk.x, (unsigned)(eidx + 0));
        if ((kk.y >> 20) == p1) st[atomicAdd(&scnt, 1)] = make_uint2(kk.y, (unsigned)(eidx + 1));
        if ((kk.z >> 20) == p1) st[atomicAdd(&scnt, 1)] = make_uint2(kk.z, (unsigned)(eidx + 2));
        if ((kk.w >> 20) == p1) st[atomicAdd(&scnt, 1)] = make_uint2(kk.w, (unsigned)(eidx + 3));
        O4[vi] = m;
    }
    __syncthreads();
    int c = scnt;
    if (c) {
        if (tid == 0) sbase = atomicAdd(&g_ccnt[row], c);
        __syncthreads();
        uint2* dst = g_cand2 + (size_t)row * NNE + sbase;
        for (int i = tid; i < c; i += 256) dst[i] = st[i];
    }
}

// ---------------- K4: finalize — levels 2/3 on candidates, scatter 1s ----------------
#define TIE_CAP 4096
__global__ void __launch_bounds__(1024) k_fin(float* __restrict__ out) {
    int row = blockIdx.x;
    int C = g_ccnt[row];
    if (C == 0) return;
    int tid = threadIdx.x;
    __shared__ unsigned h[1024];
    __shared__ unsigned ss[1024];
    __shared__ int r_bin, r_rem;
    __shared__ unsigned r_cnt;
    __shared__ unsigned tie_idx[TIE_CAP];
    __shared__ int tie_cnt;
    const uint2* cand = g_cand2 + (size_t)row * NNE;
    int rem = g_rem[row];

    // level 2: key bits [19:10]
    h[tid] = 0u;
    if (tid == 0) tie_cnt = 0;
    __syncthreads();
    for (int i = tid; i < C; i += 1024)
        atomicAdd(&h[(cand[i].x >> 10) & 1023u], 1u);
    __syncthreads();
    select_bin<1024, 1024>(h, ss, rem, &r_bin, &r_rem, &r_cnt);
    __syncthreads();
    unsigned p2 = (unsigned)r_bin;
    rem = r_rem;
    __syncthreads();

    // level 3: key bits [9:0] among bin p2
    h[tid] = 0u;
    __syncthreads();
    for (int i = tid; i < C; i += 1024) {
        unsigned kv = cand[i].x;
        if (((kv >> 10) & 1023u) == p2) atomicAdd(&h[kv & 1023u], 1u);
    }
    __syncthreads();
    select_bin<1024, 1024>(h, ss, rem, &r_bin, &r_rem, &r_cnt);
    __syncthreads();

    unsigned T = (g_p1[row] << 20) | (p2 << 10) | (unsigned)r_bin;
    int need = r_rem;            // # of key==T elements to take
    int cntT = (int)r_cnt;
    float* orow = out + (size_t)row * NNE;

    if (need == cntT) {
        // no tie at boundary: all >= T selected
        for (int i = tid; i < C; i += 1024) {
            uint2 cd = cand[i];
            if (cd.x >= T) orow[cd.y] = 1.0f;
        }
    } else {
        // select all > T; gather ==T indices into shared, rank by original index
        for (int i = tid; i < C; i += 1024) {
            uint2 cd = cand[i];
            if (cd.x > T) orow[cd.y] = 1.0f;
            else if (cd.x == T) {
                int p = atomicAdd(&tie_cnt, 1);
                if (p < TIE_CAP) tie_idx[p] = cd.y;
            }
        }
        __syncthreads();
        int tc = tie_cnt < TIE_CAP ? tie_cnt : TIE_CAP;
        // stable tie-break: lowest original index first (argsort stability)
        for (int i = tid; i < tc; i += 1024) {
            unsigned my = tie_idx[i];
            int rank = 0;
            for (int j = 0; j < tc; j++) rank += (tie_idx[j] < my);
            if (rank < need) orow[my] = 1.0f;
        }
    }
}

// ---------------- launch ----------------
extern "C" void kernel_launch(void* const* d_in, const int* in_sizes, int n_in,
                              void* d_out, int out_size) {
    // metadata order: batch (unused), t, U, D
    const float* t = (const float*)d_in[1];
    const float* U = (const float*)d_in[2];
    const float* D = (const float*)d_in[3];
    float* out = (float*)d_out;

    void* hist_ptr = nullptr;
    cudaGetSymbolAddress(&hist_ptr, g_hist1);
    cudaMemsetAsync(hist_ptr, 0, (size_t)BB * H1BINS * sizeof(unsigned));

    k_init<<<1, 256>>>(t, out);
    dim3 gkeys(8, BB);
    k_keys<<<gkeys, 256>>>(U, D);
    k_sel1<<<BB, 256>>>();
    dim3 gscan(16, BB);
    k_scan<<<gscan, 256>>>(out);
    k_fin<<<BB, 1024>>>(out);
}